// round 5
// baseline (speedup 1.0000x reference)
#include <cuda_runtime.h>
#include <math.h>

// ---------------- problem constants ----------------
#define DIMC   1024
#define B_     4
#define N_     4096
#define T_     256
#define H_     16
#define D_     64
#define INNER_ 1024
#define TK_    257       // T + 1 null token
#define ROWS_X (B_*N_)   // 16384
#define ROWS_C (B_*T_)   // 1024

// ---------------- device scratch (static, no allocations) ----------------
__device__ float g_xn[(size_t)ROWS_X*DIMC];
__device__ float g_cn[(size_t)ROWS_C*DIMC];
__device__ float g_q [(size_t)ROWS_X*INNER_];
__device__ float g_kv[(size_t)ROWS_C*2*INNER_];
__device__ float g_ao[(size_t)ROWS_X*INNER_];
__device__ float g_pr[(size_t)ROWS_X*DIMC];

// ---------------- tf32 helpers ----------------
__device__ __forceinline__ unsigned f2tf32(float x) {
    unsigned u;
    asm("cvt.rna.tf32.f32 %0, %1;" : "=r"(u) : "f"(x));
    return u;
}
__device__ __forceinline__ void mma_tf32(float c[4], const unsigned a[4], const unsigned b[2]) {
    asm volatile(
        "mma.sync.aligned.m16n8k8.row.col.f32.tf32.tf32.f32 "
        "{%0,%1,%2,%3}, {%4,%5,%6,%7}, {%8,%9}, {%0,%1,%2,%3};"
        : "+f"(c[0]), "+f"(c[1]), "+f"(c[2]), "+f"(c[3])
        : "r"(a[0]), "r"(a[1]), "r"(a[2]), "r"(a[3]), "r"(b[0]), "r"(b[1]));
}

// ---------------- LayerNorm: one block per row of 1024 ----------------
__global__ __launch_bounds__(256)
void ln_kernel(const float* __restrict__ x, const float* __restrict__ g,
               const float* __restrict__ bb, float* __restrict__ y)
{
    int row = blockIdx.x;
    int t   = threadIdx.x;
    const float4* xr = (const float4*)(x + (size_t)row * DIMC);
    float4 v = xr[t];
    float s1 = v.x + v.y + v.z + v.w;
    float s2 = v.x*v.x + v.y*v.y + v.z*v.z + v.w*v.w;
    #pragma unroll
    for (int o = 16; o; o >>= 1) {
        s1 += __shfl_xor_sync(0xffffffffu, s1, o);
        s2 += __shfl_xor_sync(0xffffffffu, s2, o);
    }
    __shared__ float sh1[8], sh2[8];
    int warp = t >> 5, lane = t & 31;
    if (lane == 0) { sh1[warp] = s1; sh2[warp] = s2; }
    __syncthreads();
    if (warp == 0) {
        s1 = (lane < 8) ? sh1[lane] : 0.f;
        s2 = (lane < 8) ? sh2[lane] : 0.f;
        #pragma unroll
        for (int o = 4; o; o >>= 1) {
            s1 += __shfl_xor_sync(0xffffffffu, s1, o);
            s2 += __shfl_xor_sync(0xffffffffu, s2, o);
        }
        if (lane == 0) {
            float mean = s1 * (1.0f / DIMC);
            float var  = s2 * (1.0f / DIMC) - mean * mean;
            sh1[0] = mean;
            sh2[0] = rsqrtf(var + 1e-5f);
        }
    }
    __syncthreads();
    float mean = sh1[0], rstd = sh2[0];
    float4 gv = ((const float4*)g)[t];
    float4 bv = ((const float4*)bb)[t];
    float4 o4;
    o4.x = (v.x - mean) * rstd * gv.x + bv.x;
    o4.y = (v.y - mean) * rstd * gv.y + bv.y;
    o4.z = (v.z - mean) * rstd * gv.z + bv.z;
    o4.w = (v.w - mean) * rstd * gv.w + bv.w;
    ((float4*)(y + (size_t)row * DIMC))[t] = o4;
}

// ---------------- tensor-core SGEMM (tf32): C[M,Nc] = A[M,K] @ W[K,Nc] ----------------
// Block tile 128x128x32, 8 warps (4M x 2N), warp 32x64.
__global__ __launch_bounds__(256, 2)
void gemm_tc(const float* __restrict__ A, const float* __restrict__ W,
             float* __restrict__ C, int K, int Nc)
{
    __shared__ unsigned As[32][132];   // [k][m]
    __shared__ unsigned Bs[32][132];   // [k][n]
    int tid = threadIdx.x, lane = tid & 31, warp = tid >> 5;
    int m0 = blockIdx.y * 128, n0 = blockIdx.x * 128;
    int wm = warp & 3, wn = warp >> 2;
    float c[2][8][4] = {};

    int ar = tid >> 3, acq = tid & 7;
    int br = tid >> 5, bcq = tid & 31;

    float4 aReg[4], bReg[4];
    const int kIters = K >> 5;

    #pragma unroll
    for (int i = 0; i < 4; i++) {
        aReg[i] = *(const float4*)&A[(size_t)(m0 + ar + i*32) * K + acq*4];
        bReg[i] = *(const float4*)&W[(size_t)(br + i*8) * Nc + n0 + bcq*4];
    }
    #pragma unroll
    for (int i = 0; i < 4; i++) {
        As[acq*4+0][ar + i*32] = f2tf32(aReg[i].x);
        As[acq*4+1][ar + i*32] = f2tf32(aReg[i].y);
        As[acq*4+2][ar + i*32] = f2tf32(aReg[i].z);
        As[acq*4+3][ar + i*32] = f2tf32(aReg[i].w);
        uint4 bw = make_uint4(f2tf32(bReg[i].x), f2tf32(bReg[i].y),
                              f2tf32(bReg[i].z), f2tf32(bReg[i].w));
        *(uint4*)&Bs[br + i*8][bcq*4] = bw;
    }
    __syncthreads();

    for (int ki = 0; ki < kIters; ki++) {
        bool more = (ki + 1) < kIters;
        if (more) {
            int k0 = (ki + 1) << 5;
            #pragma unroll
            for (int i = 0; i < 4; i++) {
                aReg[i] = *(const float4*)&A[(size_t)(m0 + ar + i*32) * K + k0 + acq*4];
                bReg[i] = *(const float4*)&W[(size_t)(k0 + br + i*8) * Nc + n0 + bcq*4];
            }
        }
        #pragma unroll
        for (int ks = 0; ks < 4; ks++) {
            int kk = ks * 8;
            unsigned af[2][4];
            #pragma unroll
            for (int mt = 0; mt < 2; mt++) {
                int m = wm*32 + mt*16 + (lane >> 2);
                int ck = kk + (lane & 3);
                af[mt][0] = As[ck][m];
                af[mt][1] = As[ck][m + 8];
                af[mt][2] = As[ck + 4][m];
                af[mt][3] = As[ck + 4][m + 8];
            }
            unsigned bf[8][2];
            #pragma unroll
            for (int nt = 0; nt < 8; nt++) {
                int n = wn*64 + nt*8 + (lane >> 2);
                bf[nt][0] = Bs[kk + (lane & 3)][n];
                bf[nt][1] = Bs[kk + 4 + (lane & 3)][n];
            }
            #pragma unroll
            for (int mt = 0; mt < 2; mt++)
                #pragma unroll
                for (int nt = 0; nt < 8; nt++)
                    mma_tf32(c[mt][nt], af[mt], bf[nt]);
        }
        __syncthreads();
        if (more) {
            #pragma unroll
            for (int i = 0; i < 4; i++) {
                As[acq*4+0][ar + i*32] = f2tf32(aReg[i].x);
                As[acq*4+1][ar + i*32] = f2tf32(aReg[i].y);
                As[acq*4+2][ar + i*32] = f2tf32(aReg[i].z);
                As[acq*4+3][ar + i*32] = f2tf32(aReg[i].w);
                uint4 bw = make_uint4(f2tf32(bReg[i].x), f2tf32(bReg[i].y),
                                      f2tf32(bReg[i].z), f2tf32(bReg[i].w));
                *(uint4*)&Bs[br + i*8][bcq*4] = bw;
            }
            __syncthreads();
        }
    }

    #pragma unroll
    for (int mt = 0; mt < 2; mt++) {
        int row = m0 + wm*32 + mt*16 + (lane >> 2);
        #pragma unroll
        for (int nt = 0; nt < 8; nt++) {
            int col = n0 + wn*64 + nt*8 + 2*(lane & 3);
            *(float2*)&C[(size_t)row * Nc + col]       = make_float2(c[mt][nt][0], c[mt][nt][1]);
            *(float2*)&C[(size_t)(row + 8) * Nc + col] = make_float2(c[mt][nt][2], c[mt][nt][3]);
        }
    }
}

// ---------------- 64-row-tile variant for small-M GEMM (KV proj) ----------------
// Block tile 64x128x32, 8 warps (2M x 4N), warp 32x32.
__global__ __launch_bounds__(256, 2)
void gemm_tc_m64(const float* __restrict__ A, const float* __restrict__ W,
                 float* __restrict__ C, int K, int Nc)
{
    __shared__ unsigned As[32][68];    // [k][m]
    __shared__ unsigned Bs[32][132];   // [k][n]
    int tid = threadIdx.x, lane = tid & 31, warp = tid >> 5;
    int m0 = blockIdx.y * 64, n0 = blockIdx.x * 128;
    int wm = warp & 1, wn = warp >> 1;
    float c[2][4][4] = {};

    int ar = tid >> 3, acq = tid & 7;   // A: 32 row-slots x 8 float4 (rows ar, ar+32)
    int br = tid >> 5, bcq = tid & 31;

    float4 aReg[2], bReg[4];
    const int kIters = K >> 5;

    #pragma unroll
    for (int i = 0; i < 2; i++)
        aReg[i] = *(const float4*)&A[(size_t)(m0 + ar + i*32) * K + acq*4];
    #pragma unroll
    for (int i = 0; i < 4; i++)
        bReg[i] = *(const float4*)&W[(size_t)(br + i*8) * Nc + n0 + bcq*4];
    #pragma unroll
    for (int i = 0; i < 2; i++) {
        As[acq*4+0][ar + i*32] = f2tf32(aReg[i].x);
        As[acq*4+1][ar + i*32] = f2tf32(aReg[i].y);
        As[acq*4+2][ar + i*32] = f2tf32(aReg[i].z);
        As[acq*4+3][ar + i*32] = f2tf32(aReg[i].w);
    }
    #pragma unroll
    for (int i = 0; i < 4; i++) {
        uint4 bw = make_uint4(f2tf32(bReg[i].x), f2tf32(bReg[i].y),
                              f2tf32(bReg[i].z), f2tf32(bReg[i].w));
        *(uint4*)&Bs[br + i*8][bcq*4] = bw;
    }
    __syncthreads();

    for (int ki = 0; ki < kIters; ki++) {
        bool more = (ki + 1) < kIters;
        if (more) {
            int k0 = (ki + 1) << 5;
            #pragma unroll
            for (int i = 0; i < 2; i++)
                aReg[i] = *(const float4*)&A[(size_t)(m0 + ar + i*32) * K + k0 + acq*4];
            #pragma unroll
            for (int i = 0; i < 4; i++)
                bReg[i] = *(const float4*)&W[(size_t)(k0 + br + i*8) * Nc + n0 + bcq*4];
        }
        #pragma unroll
        for (int ks = 0; ks < 4; ks++) {
            int kk = ks * 8;
            unsigned af[2][4];
            #pragma unroll
            for (int mt = 0; mt < 2; mt++) {
                int m = wm*32 + mt*16 + (lane >> 2);
                int ck = kk + (lane & 3);
                af[mt][0] = As[ck][m];
                af[mt][1] = As[ck][m + 8];
                af[mt][2] = As[ck + 4][m];
                af[mt][3] = As[ck + 4][m + 8];
            }
            unsigned bf[4][2];
            #pragma unroll
            for (int nt = 0; nt < 4; nt++) {
                int n = wn*32 + nt*8 + (lane >> 2);
                bf[nt][0] = Bs[kk + (lane & 3)][n];
                bf[nt][1] = Bs[kk + 4 + (lane & 3)][n];
            }
            #pragma unroll
            for (int mt = 0; mt < 2; mt++)
                #pragma unroll
                for (int nt = 0; nt < 4; nt++)
                    mma_tf32(c[mt][nt], af[mt], bf[nt]);
        }
        __syncthreads();
        if (more) {
            #pragma unroll
            for (int i = 0; i < 2; i++) {
                As[acq*4+0][ar + i*32] = f2tf32(aReg[i].x);
                As[acq*4+1][ar + i*32] = f2tf32(aReg[i].y);
                As[acq*4+2][ar + i*32] = f2tf32(aReg[i].z);
                As[acq*4+3][ar + i*32] = f2tf32(aReg[i].w);
            }
            #pragma unroll
            for (int i = 0; i < 4; i++) {
                uint4 bw = make_uint4(f2tf32(bReg[i].x), f2tf32(bReg[i].y),
                                      f2tf32(bReg[i].z), f2tf32(bReg[i].w));
                *(uint4*)&Bs[br + i*8][bcq*4] = bw;
            }
            __syncthreads();
        }
    }

    #pragma unroll
    for (int mt = 0; mt < 2; mt++) {
        int row = m0 + wm*32 + mt*16 + (lane >> 2);
        #pragma unroll
        for (int nt = 0; nt < 4; nt++) {
            int col = n0 + wn*32 + nt*8 + 2*(lane & 3);
            *(float2*)&C[(size_t)row * Nc + col]       = make_float2(c[mt][nt][0], c[mt][nt][1]);
            *(float2*)&C[(size_t)(row + 8) * Nc + col] = make_float2(c[mt][nt][2], c[mt][nt][3]);
        }
    }
}

// ================== fused flash attention (tf32) ==================
// Grid: (N_/128, B_*H_). 256 threads = 8 warps, warp w owns rows w*16..w*16+15.
// Fuses: Q l2-normalize (+q_scale), K build from KV proj + null token with
// l2-normalize (+k_scale), V build, QK^T, online softmax (SCALE=8), PV.
#define KS_OFF 0
#define VS_OFF (64*68)
#define PS_OFF (2*64*68)
#define FLASH_SMEM ((2*64*68 + 64*132) * 4)

__global__ __launch_bounds__(256)
void flash_kernel(const float* __restrict__ qv, const float* __restrict__ kvp,
                  const float* __restrict__ nullkv,
                  const float* __restrict__ qscale, const float* __restrict__ kscale,
                  float* __restrict__ O)
{
    extern __shared__ unsigned smem[];
    unsigned* Ks = smem + KS_OFF;   // [d][t]  stride 68
    unsigned* Vs = smem + VS_OFF;   // [t][d]  stride 68
    unsigned* Ps = smem + PS_OFF;   // [t][m]  stride 132  (Q staging: [d][m])

    int tid = threadIdx.x, lane = tid & 31, warp = tid >> 5;
    int bh = blockIdx.y;
    int b = bh >> 4, h = bh & 15;
    int n0 = blockIdx.x * 128;
    const float* qb = qv + (size_t)(b * N_) * INNER_ + h * 64;
    float* Ob = O + (size_t)(b * N_) * INNER_ + h * 64;

    // ---- stage Q [128 x 64] into Ps as [d][m], l2-normalized * q_scale ----
    #pragma unroll
    for (int i = 0; i < 8; i++) {
        int l = tid + i * 256;
        int m = l >> 4, cq = l & 15;      // 16 consecutive lanes share one m
        float4 v = *(const float4*)&qb[(size_t)(n0 + m) * INNER_ + cq*4];
        float ss = v.x*v.x + v.y*v.y + v.z*v.z + v.w*v.w;
        #pragma unroll
        for (int o = 8; o; o >>= 1) ss += __shfl_xor_sync(0xffffffffu, ss, o);
        float inv = 1.0f / fmaxf(sqrtf(ss), 1e-12f);
        float4 qs = *(const float4*)&qscale[cq*4];
        Ps[(cq*4+0)*132 + m] = f2tf32(v.x * inv * qs.x);
        Ps[(cq*4+1)*132 + m] = f2tf32(v.y * inv * qs.y);
        Ps[(cq*4+2)*132 + m] = f2tf32(v.z * inv * qs.z);
        Ps[(cq*4+3)*132 + m] = f2tf32(v.w * inv * qs.w);
    }
    __syncthreads();

    int m = warp * 16 + (lane >> 2);
    unsigned qf[8][4];
    #pragma unroll
    for (int kf = 0; kf < 8; kf++) {
        int ck = kf*8 + (lane & 3);
        qf[kf][0] = Ps[ck*132 + m];
        qf[kf][1] = Ps[ck*132 + m + 8];
        qf[kf][2] = Ps[(ck+4)*132 + m];
        qf[kf][3] = Ps[(ck+4)*132 + m + 8];
    }

    float m_run[2] = {-INFINITY, -INFINITY};
    float l_run[2] = {0.f, 0.f};
    float o[8][4] = {};

    for (int ch = 0; ch < 5; ch++) {
        int t0 = ch * 64;
        __syncthreads();
        // ---- stage K chunk -> Ks[d][t] (normalized * k_scale), V -> Vs[t][d] ----
        #pragma unroll
        for (int i = 0; i < 4; i++) {
            int l = tid + i * 256;
            int tr = l >> 4, cq = l & 15;  // 16 consecutive lanes share one t row
            int t = t0 + tr;
            float4 k4 = make_float4(0.f,0.f,0.f,0.f);
            float4 v4 = make_float4(0.f,0.f,0.f,0.f);
            if (t < T_) {
                const float* src = kvp + (size_t)(b * T_ + t) * (2 * INNER_) + h * 64 + cq*4;
                k4 = *(const float4*)src;
                v4 = *(const float4*)(src + INNER_);
            } else if (t < TK_) {
                k4 = *(const float4*)&nullkv[cq*4];
                v4 = *(const float4*)&nullkv[64 + cq*4];
            }
            float ss = k4.x*k4.x + k4.y*k4.y + k4.z*k4.z + k4.w*k4.w;
            #pragma unroll
            for (int ox = 8; ox; ox >>= 1) ss += __shfl_xor_sync(0xffffffffu, ss, ox);
            float inv = 1.0f / fmaxf(sqrtf(ss), 1e-12f);
            float4 ksc = *(const float4*)&kscale[cq*4];
            Ks[(cq*4+0)*68 + tr] = f2tf32(k4.x * inv * ksc.x);
            Ks[(cq*4+1)*68 + tr] = f2tf32(k4.y * inv * ksc.y);
            Ks[(cq*4+2)*68 + tr] = f2tf32(k4.z * inv * ksc.z);
            Ks[(cq*4+3)*68 + tr] = f2tf32(k4.w * inv * ksc.w);
            uint4 vw = make_uint4(f2tf32(v4.x), f2tf32(v4.y), f2tf32(v4.z), f2tf32(v4.w));
            *(uint4*)&Vs[tr*68 + cq*4] = vw;
        }
        __syncthreads();

        // ---- S = Q K^T (warp: 16 x 64) ----
        float s[8][4] = {};
        #pragma unroll
        for (int kf = 0; kf < 8; kf++) {
            int ck = kf*8 + (lane & 3);
            unsigned bf[8][2];
            #pragma unroll
            for (int nt = 0; nt < 8; nt++) {
                int n = nt*8 + (lane >> 2);
                bf[nt][0] = Ks[ck*68 + n];
                bf[nt][1] = Ks[(ck+4)*68 + n];
            }
            #pragma unroll
            for (int nt = 0; nt < 8; nt++)
                mma_tf32(s[nt], qf[kf], bf[nt]);
        }

        // ---- scale + mask + online softmax ----
        bool need_mask = (t0 + 64 > TK_);
        float cm[2] = {-INFINITY, -INFINITY};
        #pragma unroll
        for (int nt = 0; nt < 8; nt++) {
            int tcol = t0 + nt*8 + 2*(lane & 3);
            #pragma unroll
            for (int j = 0; j < 4; j++) {
                float v = s[nt][j] * 8.0f;
                if (need_mask && (tcol + (j & 1)) >= TK_) v = -INFINITY;
                s[nt][j] = v;
                int r = j >> 1;
                cm[r] = fmaxf(cm[r], v);
            }
        }
        #pragma unroll
        for (int ox = 1; ox <= 2; ox <<= 1) {
            cm[0] = fmaxf(cm[0], __shfl_xor_sync(0xffffffffu, cm[0], ox));
            cm[1] = fmaxf(cm[1], __shfl_xor_sync(0xffffffffu, cm[1], ox));
        }
        float mn[2] = {fmaxf(m_run[0], cm[0]), fmaxf(m_run[1], cm[1])};
        float alpha[2] = {__expf(m_run[0] - mn[0]), __expf(m_run[1] - mn[1])};
        float psum[2] = {0.f, 0.f};
        #pragma unroll
        for (int nt = 0; nt < 8; nt++) {
            int tl = nt*8 + 2*(lane & 3);
            float p0 = __expf(s[nt][0] - mn[0]);
            float p1 = __expf(s[nt][1] - mn[0]);
            float p2 = __expf(s[nt][2] - mn[1]);
            float p3 = __expf(s[nt][3] - mn[1]);
            psum[0] += p0 + p1;
            psum[1] += p2 + p3;
            Ps[tl*132 + m]         = f2tf32(p0);
            Ps[(tl+1)*132 + m]     = f2tf32(p1);
            Ps[tl*132 + m + 8]     = f2tf32(p2);
            Ps[(tl+1)*132 + m + 8] = f2tf32(p3);
        }
        #pragma unroll
        for (int ox = 1; ox <= 2; ox <<= 1) {
            psum[0] += __shfl_xor_sync(0xffffffffu, psum[0], ox);
            psum[1] += __shfl_xor_sync(0xffffffffu, psum[1], ox);
        }
        l_run[0] = l_run[0] * alpha[0] + psum[0];
        l_run[1] = l_run[1] * alpha[1] + psum[1];
        m_run[0] = mn[0];
        m_run[1] = mn[1];
        #pragma unroll
        for (int nt = 0; nt < 8; nt++) {
            o[nt][0] *= alpha[0]; o[nt][1] *= alpha[0];
            o[nt][2] *= alpha[1]; o[nt][3] *= alpha[1];
        }
        __syncthreads();

        // ---- O += P V (warp: 16 x 64) ----
        #pragma unroll
        for (int kf = 0; kf < 8; kf++) {
            int ck = kf*8 + (lane & 3);
            unsigned af[4];
            af[0] = Ps[ck*132 + m];
            af[1] = Ps[ck*132 + m + 8];
            af[2] = Ps[(ck+4)*132 + m];
            af[3] = Ps[(ck+4)*132 + m + 8];
            unsigned bf[8][2];
            #pragma unroll
            for (int nt = 0; nt < 8; nt++) {
                int n = nt*8 + (lane >> 2);
                bf[nt][0] = Vs[ck*68 + n];
                bf[nt][1] = Vs[(ck+4)*68 + n];
            }
            #pragma unroll
            for (int nt = 0; nt < 8; nt++)
                mma_tf32(o[nt], af, bf[nt]);
        }
    }

    // ---- final scale by 1/l and write ----
    float inv0 = 1.0f / l_run[0];
    float inv1 = 1.0f / l_run[1];
    int rowg = n0 + warp * 16 + (lane >> 2);
    #pragma unroll
    for (int nt = 0; nt < 8; nt++) {
        int col = nt*8 + 2*(lane & 3);
        *(float2*)&Ob[(size_t)rowg * INNER_ + col]       = make_float2(o[nt][0]*inv0, o[nt][1]*inv0);
        *(float2*)&Ob[(size_t)(rowg + 8) * INNER_ + col] = make_float2(o[nt][2]*inv1, o[nt][3]*inv1);
    }
}

// ---------------- launch ----------------
extern "C" void kernel_launch(void* const* d_in, const int* in_sizes, int n_in,
                              void* d_out, int out_size)
{
    const float* x      = (const float*)d_in[0];
    const float* ctx    = (const float*)d_in[1];
    const float* Wq     = (const float*)d_in[2];
    const float* Wkv    = (const float*)d_in[3];
    const float* Wo     = (const float*)d_in[4];
    const float* nullkv = (const float*)d_in[5];
    const float* qscale = (const float*)d_in[6];
    const float* kscale = (const float*)d_in[7];
    const float* ln_in_g  = (const float*)d_in[8];
    const float* ln_in_b  = (const float*)d_in[9];
    const float* ln_ctx_g = (const float*)d_in[10];
    const float* ln_ctx_b = (const float*)d_in[11];
    const float* ln_out_g = (const float*)d_in[12];
    const float* ln_out_b = (const float*)d_in[13];
    float* out = (float*)d_out;

    float *p_xn, *p_cn, *p_q, *p_kv, *p_ao, *p_pr;
    cudaGetSymbolAddress((void**)&p_xn, g_xn);
    cudaGetSymbolAddress((void**)&p_cn, g_cn);
    cudaGetSymbolAddress((void**)&p_q,  g_q);
    cudaGetSymbolAddress((void**)&p_kv, g_kv);
    cudaGetSymbolAddress((void**)&p_ao, g_ao);
    cudaGetSymbolAddress((void**)&p_pr, g_pr);

    cudaFuncSetAttribute(flash_kernel, cudaFuncAttributeMaxDynamicSharedMemorySize, FLASH_SMEM);

    // 1-2: LayerNorms
    ln_kernel<<<ROWS_X, 256>>>(x,   ln_in_g,  ln_in_b,  p_xn);
    ln_kernel<<<ROWS_C, 256>>>(ctx, ln_ctx_g, ln_ctx_b, p_cn);
    // 3: Q projection (tf32 tensor cores)
    gemm_tc<<<dim3(INNER_/128, ROWS_X/128), 256>>>(p_xn, Wq, p_q, DIMC, INNER_);
    // 4: KV projection (64-row tiles -> 256 blocks)
    gemm_tc_m64<<<dim3(2*INNER_/128, ROWS_C/64), 256>>>(p_cn, Wkv, p_kv, DIMC, 2*INNER_);
    // 5: fused attention (q-norm + kv-build + QK^T + softmax + PV)
    flash_kernel<<<dim3(N_/128, B_*H_), 256, FLASH_SMEM>>>(p_q, p_kv, nullkv, qscale, kscale, p_ao);
    // 6: output projection (tf32)
    gemm_tc<<<dim3(DIMC/128, ROWS_X/128), 256>>>(p_ao, Wo, p_pr, INNER_, DIMC);
    // 7: final LN -> d_out
    ln_kernel<<<ROWS_X, 256>>>(p_pr, ln_out_g, ln_out_b, out);
}